// round 14
// baseline (speedup 1.0000x reference)
#include <cuda_runtime.h>
#include <cuda_fp16.h>
#include <math.h>
#include <stdint.h>

// ---------------------------------------------------------------------------
// Problem constants
// ---------------------------------------------------------------------------
#define Bsz   8
#define Himg  128
#define Wimg  128
#define Cdim  192
#define HID   768
#define WS    8
#define SHIFT 4
#define NH    6
#define HD    32
#define NTOK  (Bsz*Himg*Wimg)             // 131072
#define NWIN  2048
#define NPW   64

// ---------------------------------------------------------------------------
// Scratch
// ---------------------------------------------------------------------------
__device__ __align__(16) __half g_qkv[(size_t)NTOK * 3 * Cdim];
__device__ __align__(16) __half g_att[(size_t)NTOK * Cdim];
__device__ __align__(16) __half g_ln2[(size_t)NTOK * Cdim];
__device__ __align__(16) __half g_hh [(size_t)NTOK * HID];
__device__ __align__(16) __half g_x1 [(size_t)NTOK * Cdim];   // fp16 residual
__device__ __align__(16) __half g_wh[442368];   // qkv@0 proj@110592 fc1@147456 fc2@294912

// ---------------------------------------------------------------------------
// Helpers
// ---------------------------------------------------------------------------
__device__ __forceinline__ uint32_t smem_u32(const void* p) {
    uint32_t a;
    asm("{ .reg .u64 t; cvta.to.shared.u64 t, %1; cvt.u32.u64 %0, t; }" : "=r"(a) : "l"(p));
    return a;
}
__device__ __forceinline__ void cp_async16(uint32_t dst, const void* src) {
    asm volatile("cp.async.cg.shared.global [%0], [%1], 16;" :: "r"(dst), "l"(src) : "memory");
}
__device__ __forceinline__ void sts32(uint32_t addr, uint32_t v) {
    asm volatile("st.shared.b32 [%0], %1;" :: "r"(addr), "r"(v) : "memory");
}
__device__ __forceinline__ void ldsm4(uint32_t* r, uint32_t addr) {
    asm volatile("ldmatrix.sync.aligned.m8n8.x4.shared.b16 {%0,%1,%2,%3}, [%4];"
        : "=r"(r[0]), "=r"(r[1]), "=r"(r[2]), "=r"(r[3]) : "r"(addr));
}
__device__ __forceinline__ void mma16(float* c, const uint32_t* a, const uint32_t* b) {
    asm volatile("mma.sync.aligned.m16n8k16.row.col.f32.f16.f16.f32 "
        "{%0,%1,%2,%3}, {%4,%5,%6,%7}, {%8,%9}, {%0,%1,%2,%3};"
        : "+f"(c[0]), "+f"(c[1]), "+f"(c[2]), "+f"(c[3])
        : "r"(a[0]), "r"(a[1]), "r"(a[2]), "r"(a[3]), "r"(b[0]), "r"(b[1]));
}
__device__ __forceinline__ long win2orig(long t) {
    const int b_ = (int)(t >> 6), n = (int)(t & 63);
    const int b = b_ >> 8, wi = b_ & 255;
    const int h = ((wi >> 4) * 8 + (n >> 3) + SHIFT) & 127;
    const int w = ((wi & 15) * 8 + (n & 7) + SHIFT) & 127;
    return ((long)b * 128 + h) * 128 + w;
}
// Branchless GELU: Abramowitz-Stegun 7.1.26 erf approx (|err| < 1.5e-7)
__device__ __forceinline__ float gelu1(float x) {
    const float z  = 0.7071067811865475f * x;
    const float az = fabsf(z);
    const float t  = __fdividef(1.f, 1.f + 0.3275911f * az);
    float p = 1.061405429f;
    p = p * t - 1.453152027f;
    p = p * t + 1.421413741f;
    p = p * t - 0.284496736f;
    p = p * t + 0.254829592f;
    p = p * t;
    const float e  = __expf(-z * z);
    float er = 1.f - p * e;
    er = copysignf(er, z);
    return 0.5f * x * (1.f + er);
}

#define ACH 8192       // 64 rows x 128B
#define BCH 24576      // 192 rows x 128B
#define NTH 256

// 8 warps: 2m x 4n, warp tile 32x48, M-tile 64
#define DECOMP() \
    const int tid  = threadIdx.x; \
    const int wid  = tid >> 5; \
    const int lane = tid & 31; \
    const int g    = lane >> 2; \
    const int tig  = lane & 3; \
    const int m0w  = (wid >> 2) * 32; \
    const int n0w  = (wid & 3) * 48;

#define LDSM_SETUP() \
    const int l8 = lane & 7; \
    const int aHi = lane >> 4; \
    const uint32_t aOff0 = (uint32_t)(m0w + l8 + ((lane >> 3) & 1) * 8) * 128; \
    const int bHi = (lane >> 3) & 1; \
    const uint32_t bOff0 = (uint32_t)(n0w + l8 + ((lane >> 4) & 1) * 8) * 128;

#define KCHUNK_MMA(aB, bB) \
    _Pragma("unroll") \
    for (int s = 0; s < 4; s++) { \
        const uint32_t ac = (uint32_t)(((2 * s + aHi) ^ l8) << 4); \
        const uint32_t bc = (uint32_t)(((2 * s + bHi) ^ l8) << 4); \
        uint32_t af[2][4], bp[3][4]; \
        _Pragma("unroll") \
        for (int mi = 0; mi < 2; mi++) ldsm4(af[mi], (aB) + aOff0 + mi * 2048 + ac); \
        _Pragma("unroll") \
        for (int p = 0; p < 3; p++)  ldsm4(bp[p], (bB) + bOff0 + p * 2048 + bc); \
        _Pragma("unroll") \
        for (int mi = 0; mi < 2; mi++) \
            _Pragma("unroll") \
            for (int ni = 0; ni < 6; ni++) \
                mma16(acc[mi][ni], af[mi], &bp[ni >> 1][(ni & 1) * 2]); \
    }

#define CLEAR_ACC() \
    _Pragma("unroll") \
    for (int mi = 0; mi < 2; mi++) \
        _Pragma("unroll") \
        for (int ni = 0; ni < 6; ni++) \
            _Pragma("unroll") \
            for (int c = 0; c < 4; c++) acc[mi][ni][c] = 0.f;

// B chunk loader: 192 rows, 256 threads -> 6 iterations of 32 rows. buf in {0,1,2}
#define ISSUE_B(buf, nt, c) do { \
        const uint32_t bd = bBase + (uint32_t)(buf) * BCH + (uint32_t)lm * 128 + bswz; \
        const __half* sb_ = B + ((long)(nt) * 192 + lm) * Cdim + (c) * 64 + lq * 8; \
        _Pragma("unroll") \
        for (int it = 0; it < 6; it++) \
            cp_async16(bd + it * 4096, sb_ + (long)it * 32 * Cdim); \
        asm volatile("cp.async.commit_group;" ::: "memory"); \
    } while (0)

#define WAITG(ci, total) do { \
        if ((ci) == (total) - 1) asm volatile("cp.async.wait_group 0;" ::: "memory"); \
        else                     asm volatile("cp.async.wait_group 1;" ::: "memory"); \
    } while (0)

// ---------------------------------------------------------------------------
// Fused LN + GEMM (QKV): M-tile 64; A = LN(gather(x)) resident (3 chunks)
// ---------------------------------------------------------------------------
#define LN_SMEM (3*ACH + 3*BCH + 128)

__global__ void __launch_bounds__(NTH, 2)
gemm_ln(const float* __restrict__ Asrc, const __half* __restrict__ B,
        const float* __restrict__ bias, const float* __restrict__ gamma,
        const float* __restrict__ beta, __half* __restrict__ C, int N)
{
    extern __shared__ char dsm[];
    const uint32_t base  = (smem_u32(dsm) + 127u) & ~127u;
    const uint32_t bBase = base + 3 * ACH;

    DECOMP();
    LDSM_SETUP();
    const long m0 = (long)blockIdx.x * 64;
    const int lm = tid >> 3;
    const int lq = tid & 7;
    const uint32_t bswz = (uint32_t)((lq ^ (lm & 7)) << 4);
    const int NT = N / 192;
    const int total = NT * 3;

    ISSUE_B(0, 0, 0);
    ISSUE_B(1, 0, 1);

    // LN prologue: 8 warps x 8 rows = 64 rows
#pragma unroll 1
    for (int rr = 0; rr < 8; rr++) {
        const int row = wid * 8 + rr;
        const long t = m0 + row;
        const float* src = Asrc + win2orig(t) * Cdim;
        float2 v[3];
        float s = 0.f, ss = 0.f;
#pragma unroll
        for (int i = 0; i < 3; i++) {
            v[i] = *(const float2*)(src + 2 * lane + 64 * i);
            s  += v[i].x + v[i].y;
            ss += v[i].x * v[i].x + v[i].y * v[i].y;
        }
#pragma unroll
        for (int o = 16; o > 0; o >>= 1) {
            s  += __shfl_xor_sync(0xffffffffu, s,  o);
            ss += __shfl_xor_sync(0xffffffffu, ss, o);
        }
        const float mu  = s * (1.f / Cdim);
        const float var = ss * (1.f / Cdim) - mu * mu;
        const float r   = rsqrtf(var + 1e-5f);
        const uint32_t rowaddr = base + (uint32_t)row * 128 +
            ((((uint32_t)lane >> 2) ^ ((uint32_t)row & 7)) << 4) + ((uint32_t)lane & 3) * 4;
#pragma unroll
        for (int i = 0; i < 3; i++) {
            const int c = 2 * lane + 64 * i;
            const float2 gm = *(const float2*)(gamma + c);
            const float2 bt = *(const float2*)(beta + c);
            const __half2 hv = __floats2half2_rn((v[i].x - mu) * r * gm.x + bt.x,
                                                 (v[i].y - mu) * r * gm.y + bt.y);
            sts32(rowaddr + (uint32_t)i * ACH, *(const uint32_t*)&hv);
        }
    }

    float acc[2][6][4];
    CLEAR_ACC();

    for (int ci = 0; ci < total; ci++) {
        const int c = ci % 3;
        WAITG(ci, total);
        __syncthreads();
        if (ci + 2 < total) {
            const int cn = ci + 2;
            ISSUE_B(cn % 3, cn / 3, cn % 3);
        }

        KCHUNK_MMA(base + (uint32_t)c * ACH, bBase + (uint32_t)(ci % 3) * BCH);

        if (c == 2) {
            const int nt = ci / 3;
#pragma unroll
            for (int mi = 0; mi < 2; mi++) {
                const long r0 = m0 + m0w + mi * 16 + g;
                const long r1 = r0 + 8;
#pragma unroll
                for (int ni = 0; ni < 6; ni++) {
                    const int col = nt * 192 + n0w + ni * 8 + 2 * tig;
                    const float b0 = bias[col], b1 = bias[col + 1];
                    *(__half2*)(C + r0 * N + col) =
                        __floats2half2_rn(acc[mi][ni][0] + b0, acc[mi][ni][1] + b1);
                    *(__half2*)(C + r1 * N + col) =
                        __floats2half2_rn(acc[mi][ni][2] + b0, acc[mi][ni][3] + b1);
                    acc[mi][ni][0] = 0.f; acc[mi][ni][1] = 0.f;
                    acc[mi][ni][2] = 0.f; acc[mi][ni][3] = 0.f;
                }
            }
        }
    }
}

// ---------------------------------------------------------------------------
// A-resident fp16 GEMM (FC1): M-tile 64; C = GELU(A @ B^T + bias), half out
// ---------------------------------------------------------------------------
#define HA_SMEM (3*ACH + 3*BCH + 128)

__global__ void __launch_bounds__(NTH, 2)
gemm_ha(const __half* __restrict__ A, const __half* __restrict__ B,
        const float* __restrict__ bias, __half* __restrict__ C, int N)
{
    extern __shared__ char dsm[];
    const uint32_t base  = (smem_u32(dsm) + 127u) & ~127u;
    const uint32_t bBase = base + 3 * ACH;

    DECOMP();
    LDSM_SETUP();
    const long m0 = (long)blockIdx.x * 64;
    const int lm = tid >> 3;
    const int lq = tid & 7;
    const uint32_t bswz = (uint32_t)((lq ^ (lm & 7)) << 4);
    const int NT = N / 192;
    const int total = NT * 3;

    {
        const uint32_t da = base + (uint32_t)lm * 128 + bswz;
        const __half* sa = A + (m0 + lm) * Cdim + lq * 8;
#pragma unroll
        for (int c = 0; c < 3; c++)
#pragma unroll
            for (int it = 0; it < 2; it++)
                cp_async16(da + (uint32_t)c * ACH + it * 4096,
                           sa + (long)it * 32 * Cdim + c * 64);
        asm volatile("cp.async.commit_group;" ::: "memory");
    }

    ISSUE_B(0, 0, 0);
    ISSUE_B(1, 0, 1);

    float acc[2][6][4];
    CLEAR_ACC();

    for (int ci = 0; ci < total; ci++) {
        const int c = ci % 3;
        WAITG(ci, total);
        __syncthreads();
        if (ci + 2 < total) {
            const int cn = ci + 2;
            ISSUE_B(cn % 3, cn / 3, cn % 3);
        }

        KCHUNK_MMA(base + (uint32_t)c * ACH, bBase + (uint32_t)(ci % 3) * BCH);

        if (c == 2) {
            const int nt = ci / 3;
#pragma unroll
            for (int mi = 0; mi < 2; mi++) {
                const long r0 = m0 + m0w + mi * 16 + g;
                const long r1 = r0 + 8;
#pragma unroll
                for (int ni = 0; ni < 6; ni++) {
                    const int col = nt * 192 + n0w + ni * 8 + 2 * tig;
                    const float b0 = bias[col], b1 = bias[col + 1];
                    const float v0 = gelu1(acc[mi][ni][0] + b0);
                    const float v1 = gelu1(acc[mi][ni][1] + b1);
                    const float v2 = gelu1(acc[mi][ni][2] + b0);
                    const float v3 = gelu1(acc[mi][ni][3] + b1);
                    *(__half2*)(C + r0 * N + col) = __floats2half2_rn(v0, v1);
                    *(__half2*)(C + r1 * N + col) = __floats2half2_rn(v2, v3);
                    acc[mi][ni][0] = 0.f; acc[mi][ni][1] = 0.f;
                    acc[mi][ni][2] = 0.f; acc[mi][ni][3] = 0.f;
                }
            }
        }
    }
}

// ---------------------------------------------------------------------------
// Streaming fp16 GEMM, M-tile 64, triple-buffered.
// EPI=2: FC2 (+x1 res fp16 -> out fp32).
// EPI=3: proj (unshift + x res fp32 -> x1 fp16, LN2 -> ln2 fp16)
// ---------------------------------------------------------------------------
#define STAGE  (ACH + BCH)
#define GEMM_SMEM (3*STAGE + 128)

template <int EPI>
__global__ void __launch_bounds__(NTH, 2)
gemm_h(const __half* __restrict__ A, const __half* __restrict__ Bw,
       const float* __restrict__ bias, const void* __restrict__ resv,
       void* __restrict__ Cv, __half* __restrict__ C2,
       const float* __restrict__ gamma, const float* __restrict__ beta,
       int N, int K)
{
    extern __shared__ char dsm[];
    const uint32_t base = (smem_u32(dsm) + 127u) & ~127u;

    DECOMP();
    LDSM_SETUP();
    const long m0 = (long)blockIdx.x * 64;

    const int lm = tid >> 3;
    const int lq = tid & 7;
    const __half* srcA = A + (m0 + lm) * K + lq * 8;
    const __half* srcB = Bw + (long)lm * K + lq * 8;
    const uint32_t swz = (uint32_t)((lq ^ (lm & 7)) << 4);
    const uint32_t dstA0 = base + (uint32_t)lm * 128 + swz;
    const uint32_t dstB0 = base + ACH + (uint32_t)lm * 128 + swz;

    float acc[2][6][4];
    CLEAR_ACC();

    const int NC = K >> 6;

#define ISSUE(buf, kc_) do { \
        const uint32_t so = (uint32_t)(buf) * STAGE; \
        const __half* sa = srcA + (kc_); \
        const __half* sb_ = srcB + (kc_); \
        _Pragma("unroll") \
        for (int it = 0; it < 2; it++) \
            cp_async16(dstA0 + so + it * 4096, sa + (long)it * 32 * K); \
        _Pragma("unroll") \
        for (int it = 0; it < 6; it++) \
            cp_async16(dstB0 + so + it * 4096, sb_ + (long)it * 32 * K); \
        asm volatile("cp.async.commit_group;" ::: "memory"); \
    } while (0)

    ISSUE(0, 0);
    if (NC > 1) ISSUE(1, 64);

    for (int i = 0; i < NC; i++) {
        WAITG(i, NC);
        __syncthreads();
        if (i + 2 < NC) ISSUE((i + 2) % 3, (i + 2) << 6);

        const uint32_t so = (uint32_t)(i % 3) * STAGE;
        KCHUNK_MMA(base + so, base + ACH + so);
    }
#undef ISSUE

    // bias + residual into acc
#pragma unroll
    for (int mi = 0; mi < 2; mi++) {
        const long rw0 = m0 + m0w + mi * 16 + g;
        const long r0 = (EPI == 3) ? win2orig(rw0) : rw0;
        const long r1 = (EPI == 3) ? win2orig(rw0 + 8) : (rw0 + 8);
#pragma unroll
        for (int ni = 0; ni < 6; ni++) {
            const int col = n0w + ni * 8 + 2 * tig;
            const float b0 = bias[col], b1 = bias[col + 1];
            float rax, ray, rbx, rby;
            if (EPI == 3) {
                const float* res = (const float*)resv;
                const float2 ra = *(const float2*)(res + r0 * N + col);
                const float2 rb = *(const float2*)(res + r1 * N + col);
                rax = ra.x; ray = ra.y; rbx = rb.x; rby = rb.y;
            } else {
                const __half* res = (const __half*)resv;
                const float2 ra = __half22float2(*(const __half2*)(res + r0 * N + col));
                const float2 rb = __half22float2(*(const __half2*)(res + r1 * N + col));
                rax = ra.x; ray = ra.y; rbx = rb.x; rby = rb.y;
            }
            acc[mi][ni][0] += b0 + rax;
            acc[mi][ni][1] += b1 + ray;
            acc[mi][ni][2] += b0 + rbx;
            acc[mi][ni][3] += b1 + rby;
        }
    }

    if (EPI == 3) {
        float* rsum   = (float*)(dsm);
        float* rsumsq = rsum + 64;
        __syncthreads();
        if (tid < 64) { rsum[tid] = 0.f; rsumsq[tid] = 0.f; }
        __syncthreads();
#pragma unroll
        for (int mi = 0; mi < 2; mi++) {
            const int row0 = m0w + mi * 16 + g;
            float s0 = 0.f, q0 = 0.f, s1 = 0.f, q1 = 0.f;
#pragma unroll
            for (int ni = 0; ni < 6; ni++) {
                s0 += acc[mi][ni][0] + acc[mi][ni][1];
                q0 += acc[mi][ni][0] * acc[mi][ni][0] + acc[mi][ni][1] * acc[mi][ni][1];
                s1 += acc[mi][ni][2] + acc[mi][ni][3];
                q1 += acc[mi][ni][2] * acc[mi][ni][2] + acc[mi][ni][3] * acc[mi][ni][3];
            }
            atomicAdd(&rsum[row0], s0);     atomicAdd(&rsumsq[row0], q0);
            atomicAdd(&rsum[row0 + 8], s1); atomicAdd(&rsumsq[row0 + 8], q1);
        }
        __syncthreads();
    }

#pragma unroll
    for (int mi = 0; mi < 2; mi++) {
        const long rw0 = m0 + m0w + mi * 16 + g;
        const long r0 = (EPI == 3) ? win2orig(rw0) : rw0;
        const long r1 = (EPI == 3) ? win2orig(rw0 + 8) : (rw0 + 8);

        float mu0 = 0.f, rs0 = 0.f, mu1 = 0.f, rs1 = 0.f;
        if (EPI == 3) {
            const float* rsum   = (const float*)(dsm);
            const float* rsumsq = rsum + 64;
            const int row0 = m0w + mi * 16 + g;
            mu0 = rsum[row0] * (1.f / Cdim);
            rs0 = rsqrtf(rsumsq[row0] * (1.f / Cdim) - mu0 * mu0 + 1e-5f);
            mu1 = rsum[row0 + 8] * (1.f / Cdim);
            rs1 = rsqrtf(rsumsq[row0 + 8] * (1.f / Cdim) - mu1 * mu1 + 1e-5f);
        }
#pragma unroll
        for (int ni = 0; ni < 6; ni++) {
            const int col = n0w + ni * 8 + 2 * tig;
            const float v0 = acc[mi][ni][0], v1 = acc[mi][ni][1];
            const float v2 = acc[mi][ni][2], v3 = acc[mi][ni][3];
            if (EPI == 3) {
                __half* C = (__half*)Cv;
                *(__half2*)(C + r0 * N + col) = __floats2half2_rn(v0, v1);
                *(__half2*)(C + r1 * N + col) = __floats2half2_rn(v2, v3);
                const float2 gm = *(const float2*)(gamma + col);
                const float2 bt = *(const float2*)(beta + col);
                *(__half2*)(C2 + r0 * N + col) = __floats2half2_rn(
                    (v0 - mu0) * rs0 * gm.x + bt.x, (v1 - mu0) * rs0 * gm.y + bt.y);
                *(__half2*)(C2 + r1 * N + col) = __floats2half2_rn(
                    (v2 - mu1) * rs1 * gm.x + bt.x, (v3 - mu1) * rs1 * gm.y + bt.y);
            } else {
                float* C = (float*)Cv;
                *(float2*)(C + r0 * N + col) = make_float2(v0, v1);
                *(float2*)(C + r1 * N + col) = make_float2(v2, v3);
            }
        }
    }
}

// ---------------------------------------------------------------------------
// One-shot weight conversion fp32 -> fp16 (4 tensors)
// ---------------------------------------------------------------------------
__global__ void tohalf_all(const float* __restrict__ s0, const float* __restrict__ s1,
                           const float* __restrict__ s2, const float* __restrict__ s3,
                           __half* __restrict__ dst)
{
    const int i = blockIdx.x * 1024 + threadIdx.x * 4;
    const float* src;
    int off;
    if (i < 110592)      { src = s0; off = 0; }
    else if (i < 147456) { src = s1; off = 110592; }
    else if (i < 294912) { src = s2; off = 147456; }
    else                 { src = s3; off = 294912; }
    const float4 v = *(const float4*)(src + (i - off));
    __half2* d = (__half2*)(dst + i);
    d[0] = __floats2half2_rn(v.x, v.y);
    d[1] = __floats2half2_rn(v.z, v.w);
}

// ---------------------------------------------------------------------------
// Fused window attention v2. Block per (window, head), 64 threads.
// ---------------------------------------------------------------------------
__global__ void __launch_bounds__(64, 16)
attn_kernel(const __half* __restrict__ qkv,
            const float* __restrict__ rpb,
            __half* __restrict__ out)
{
    const int win  = blockIdx.x;
    const int head = blockIdx.y;
    const int n    = threadIdx.x;

    __shared__ __half2 ks[64][20];
    __shared__ __half2 vs[64][20];
    __shared__ __half  sp[64][66];
    __shared__ float   sbias[225];
    __shared__ int     lab[64];

    const __half* base = qkv + (long)win * NPW * (3 * Cdim);
    const __half2* k2 = (const __half2*)(base + n * (3 * Cdim) + Cdim + head * HD);
    const __half2* v2 = (const __half2*)(base + n * (3 * Cdim) + 2 * Cdim + head * HD);
#pragma unroll
    for (int dp = 0; dp < 16; dp++) {
        ks[n][dp] = k2[dp];
        vs[n][dp] = v2[dp];
    }
    for (int idx = n; idx < 225; idx += 64) sbias[idx] = rpb[idx * NH + head];
    {
        const int wi = win & 255;
        const int gh = (wi >> 4) * 8 + (n >> 3);
        const int gw = (wi & 15) * 8 + (n & 7);
        const int rh = (gh < Himg - WS) ? 0 : ((gh < Himg - SHIFT) ? 1 : 2);
        const int rw = (gw < Wimg - WS) ? 0 : ((gw < Wimg - SHIFT) ? 1 : 2);
        lab[n] = rh * 3 + rw;
    }
    __syncthreads();

    float q[HD];
    const __half2* q2 = (const __half2*)(base + n * (3 * Cdim) + head * HD);
#pragma unroll
    for (int dp = 0; dp < 16; dp++) {
        const float2 f = __half22float2(q2[dp]);
        q[2 * dp]     = f.x * 0.17677669529663687f;
        q[2 * dp + 1] = f.y * 0.17677669529663687f;
    }

    const int i = n >> 3, j = n & 7;
    const int myl = lab[n];

    float sc[64];
    float mx = -1e30f;
#pragma unroll 4
    for (int m = 0; m < 64; m++) {
        const __half2* kr = &ks[m][0];
        float s = 0.f;
#pragma unroll
        for (int t = 0; t < 16; t++) {
            const float2 kv = __half22float2(kr[t]);
            s += q[2*t] * kv.x + q[2*t+1] * kv.y;
        }
        s += sbias[(i - (m >> 3) + 7) * 15 + (j - (m & 7) + 7)];
        if (lab[m] != myl) s -= 100.f;
        sc[m] = s;
        mx = fmaxf(mx, s);
    }
    float sum = 0.f;
#pragma unroll 4
    for (int m = 0; m < 64; m++) {
        const float e = __expf(sc[m] - mx);
        sc[m] = e;
        sum += e;
    }
    const float inv = __fdividef(1.f, sum);
#pragma unroll 4
    for (int m = 0; m < 64; m++)
        sp[n][m] = __float2half_rn(sc[m] * inv);
    __syncwarp();

    float accv[HD];
#pragma unroll
    for (int d = 0; d < HD; d++) accv[d] = 0.f;
#pragma unroll 2
    for (int m = 0; m < 64; m++) {
        const float p = __half2float(sp[n][m]);
        const __half2* vr = &vs[m][0];
#pragma unroll
        for (int t = 0; t < 16; t++) {
            const float2 vv = __half22float2(vr[t]);
            accv[2*t]   += p * vv.x;
            accv[2*t+1] += p * vv.y;
        }
    }
    __half* dst = out + ((long)win * NPW + n) * Cdim + head * HD;
#pragma unroll
    for (int dp = 0; dp < 16; dp++)
        *(__half2*)(dst + 2 * dp) = __floats2half2_rn(accv[2*dp], accv[2*dp+1]);
}

// ---------------------------------------------------------------------------
// Launch
// ---------------------------------------------------------------------------
extern "C" void kernel_launch(void* const* d_in, const int* in_sizes, int n_in,
                              void* d_out, int out_size)
{
    const float* x      = (const float*)d_in[0];
    const float* g1     = (const float*)d_in[1];
    const float* b1     = (const float*)d_in[2];
    const float* qkv_w  = (const float*)d_in[3];
    const float* qkv_b  = (const float*)d_in[4];
    const float* rpb    = (const float*)d_in[5];
    const float* proj_w = (const float*)d_in[6];
    const float* proj_b = (const float*)d_in[7];
    const float* g2     = (const float*)d_in[8];
    const float* b2     = (const float*)d_in[9];
    const float* fc1_w  = (const float*)d_in[10];
    const float* fc1_b  = (const float*)d_in[11];
    const float* fc2_w  = (const float*)d_in[12];
    const float* fc2_b  = (const float*)d_in[13];
    float* out = (float*)d_out;

    __half *p_qkv, *p_att, *p_ln2, *p_hh, *p_x1, *p_wh;
    cudaGetSymbolAddress((void**)&p_qkv, g_qkv);
    cudaGetSymbolAddress((void**)&p_att, g_att);
    cudaGetSymbolAddress((void**)&p_ln2, g_ln2);
    cudaGetSymbolAddress((void**)&p_hh,  g_hh);
    cudaGetSymbolAddress((void**)&p_x1,  g_x1);
    cudaGetSymbolAddress((void**)&p_wh,  g_wh);

    static bool attr_set = false;
    if (!attr_set) {
        cudaFuncSetAttribute(gemm_ln,   cudaFuncAttributeMaxDynamicSharedMemorySize, LN_SMEM);
        cudaFuncSetAttribute(gemm_ha,   cudaFuncAttributeMaxDynamicSharedMemorySize, HA_SMEM);
        cudaFuncSetAttribute(gemm_h<3>, cudaFuncAttributeMaxDynamicSharedMemorySize, GEMM_SMEM);
        cudaFuncSetAttribute(gemm_h<2>, cudaFuncAttributeMaxDynamicSharedMemorySize, GEMM_SMEM);
        attr_set = true;
    }

    __half* w_qkv = p_wh;
    __half* w_prj = p_wh + 110592;
    __half* w_fc1 = p_wh + 147456;
    __half* w_fc2 = p_wh + 294912;

    // 0. weights fp32 -> fp16
    tohalf_all<<<442368 / 1024, 256>>>(qkv_w, proj_w, fc1_w, fc2_w, p_wh);

    const int M = NTOK;  // 131072, 2048 M-tiles of 64

    // 1. QKV (fused LN1 + shift/window gather)
    gemm_ln<<<M / 64, NTH, LN_SMEM>>>(x, w_qkv, qkv_b, g1, b1, p_qkv, 3 * Cdim);

    // 2. Window attention
    attn_kernel<<<dim3(NWIN, NH), 64>>>(p_qkv, rpb, p_att);

    // 3. proj + unshift + x residual -> x1 fp16; fused LN2 -> ln2 fp16
    gemm_h<3><<<M / 64, NTH, GEMM_SMEM>>>(
        p_att, w_prj, proj_b, x, p_x1, p_ln2, g2, b2, Cdim, Cdim);

    // 4. FC1 + GELU (A-resident)
    gemm_ha<<<M / 64, NTH, HA_SMEM>>>(p_ln2, w_fc1, fc1_b, p_hh, HID);

    // 5. FC2 + x1 residual (fp16) -> out fp32
    gemm_h<2><<<M / 64, NTH, GEMM_SMEM>>>(
        p_hh, w_fc2, fc2_b, p_x1, out, nullptr, nullptr, nullptr, Cdim, HID);
}

// round 15
// speedup vs baseline: 1.1229x; 1.1229x over previous
#include <cuda_runtime.h>
#include <cuda_fp16.h>
#include <math.h>
#include <stdint.h>

// ---------------------------------------------------------------------------
// Problem constants
// ---------------------------------------------------------------------------
#define Bsz   8
#define Himg  128
#define Wimg  128
#define Cdim  192
#define HID   768
#define WS    8
#define SHIFT 4
#define NH    6
#define HD    32
#define NTOK  (Bsz*Himg*Wimg)             // 131072
#define NWIN  2048
#define NPW   64

// ---------------------------------------------------------------------------
// Scratch
// ---------------------------------------------------------------------------
__device__ __align__(16) __half g_qkv[(size_t)NTOK * 3 * Cdim];
__device__ __align__(16) __half g_att[(size_t)NTOK * Cdim];
__device__ __align__(16) __half g_ln2[(size_t)NTOK * Cdim];
__device__ __align__(16) __half g_hh [(size_t)NTOK * HID];
__device__ __align__(16) float  g_x1 [(size_t)NTOK * Cdim];
__device__ __align__(16) __half g_wh[442368];   // qkv@0 proj@110592 fc1@147456 fc2@294912

// ---------------------------------------------------------------------------
// Helpers
// ---------------------------------------------------------------------------
__device__ __forceinline__ uint32_t smem_u32(const void* p) {
    uint32_t a;
    asm("{ .reg .u64 t; cvta.to.shared.u64 t, %1; cvt.u32.u64 %0, t; }" : "=r"(a) : "l"(p));
    return a;
}
__device__ __forceinline__ void cp_async16(uint32_t dst, const void* src) {
    asm volatile("cp.async.cg.shared.global [%0], [%1], 16;" :: "r"(dst), "l"(src) : "memory");
}
__device__ __forceinline__ void sts32(uint32_t addr, uint32_t v) {
    asm volatile("st.shared.b32 [%0], %1;" :: "r"(addr), "r"(v) : "memory");
}
__device__ __forceinline__ void ldsm4(uint32_t* r, uint32_t addr) {
    asm volatile("ldmatrix.sync.aligned.m8n8.x4.shared.b16 {%0,%1,%2,%3}, [%4];"
        : "=r"(r[0]), "=r"(r[1]), "=r"(r[2]), "=r"(r[3]) : "r"(addr));
}
__device__ __forceinline__ void mma16(float* c, const uint32_t* a, const uint32_t* b) {
    asm volatile("mma.sync.aligned.m16n8k16.row.col.f32.f16.f16.f32 "
        "{%0,%1,%2,%3}, {%4,%5,%6,%7}, {%8,%9}, {%0,%1,%2,%3};"
        : "+f"(c[0]), "+f"(c[1]), "+f"(c[2]), "+f"(c[3])
        : "r"(a[0]), "r"(a[1]), "r"(a[2]), "r"(a[3]), "r"(b[0]), "r"(b[1]));
}
__device__ __forceinline__ long win2orig(long t) {
    const int b_ = (int)(t >> 6), n = (int)(t & 63);
    const int b = b_ >> 8, wi = b_ & 255;
    const int h = ((wi >> 4) * 8 + (n >> 3) + SHIFT) & 127;
    const int w = ((wi & 15) * 8 + (n & 7) + SHIFT) & 127;
    return ((long)b * 128 + h) * 128 + w;
}
// Branchless GELU: Abramowitz-Stegun 7.1.26 erf approx (|err| < 1.5e-7)
__device__ __forceinline__ float gelu1(float x) {
    const float z  = 0.7071067811865475f * x;
    const float az = fabsf(z);
    const float t  = __fdividef(1.f, 1.f + 0.3275911f * az);
    float p = 1.061405429f;
    p = p * t - 1.453152027f;
    p = p * t + 1.421413741f;
    p = p * t - 0.284496736f;
    p = p * t + 0.254829592f;
    p = p * t;
    const float e  = __expf(-z * z);
    float er = 1.f - p * e;
    er = copysignf(er, z);
    return 0.5f * x * (1.f + er);
}

#define ACH 8192       // 64 rows x 128B
#define BCH 24576      // 192 rows x 128B
#define NTH 256

// 8 warps: 2m x 4n, warp tile 32x48, M-tile 64
#define DECOMP() \
    const int tid  = threadIdx.x; \
    const int wid  = tid >> 5; \
    const int lane = tid & 31; \
    const int g    = lane >> 2; \
    const int tig  = lane & 3; \
    const int m0w  = (wid >> 2) * 32; \
    const int n0w  = (wid & 3) * 48;

#define LDSM_SETUP() \
    const int l8 = lane & 7; \
    const int aHi = lane >> 4; \
    const uint32_t aOff0 = (uint32_t)(m0w + l8 + ((lane >> 3) & 1) * 8) * 128; \
    const int bHi = (lane >> 3) & 1; \
    const uint32_t bOff0 = (uint32_t)(n0w + l8 + ((lane >> 4) & 1) * 8) * 128;

#define KCHUNK_MMA(aB, bB) \
    _Pragma("unroll") \
    for (int s = 0; s < 4; s++) { \
        const uint32_t ac = (uint32_t)(((2 * s + aHi) ^ l8) << 4); \
        const uint32_t bc = (uint32_t)(((2 * s + bHi) ^ l8) << 4); \
        uint32_t af[2][4], bp[3][4]; \
        _Pragma("unroll") \
        for (int mi = 0; mi < 2; mi++) ldsm4(af[mi], (aB) + aOff0 + mi * 2048 + ac); \
        _Pragma("unroll") \
        for (int p = 0; p < 3; p++)  ldsm4(bp[p], (bB) + bOff0 + p * 2048 + bc); \
        _Pragma("unroll") \
        for (int mi = 0; mi < 2; mi++) \
            _Pragma("unroll") \
            for (int ni = 0; ni < 6; ni++) \
                mma16(acc[mi][ni], af[mi], &bp[ni >> 1][(ni & 1) * 2]); \
    }

#define CLEAR_ACC() \
    _Pragma("unroll") \
    for (int mi = 0; mi < 2; mi++) \
        _Pragma("unroll") \
        for (int ni = 0; ni < 6; ni++) \
            _Pragma("unroll") \
            for (int c = 0; c < 4; c++) acc[mi][ni][c] = 0.f;

// B chunk loader: 192 rows, 256 threads -> 6 iterations of 32 rows. buf in {0,1,2}
#define ISSUE_B(buf, nt, c) do { \
        const uint32_t bd = bBase + (uint32_t)(buf) * BCH + (uint32_t)lm * 128 + bswz; \
        const __half* sb_ = B + ((long)(nt) * 192 + lm) * Cdim + (c) * 64 + lq * 8; \
        _Pragma("unroll") \
        for (int it = 0; it < 6; it++) \
            cp_async16(bd + it * 4096, sb_ + (long)it * 32 * Cdim); \
        asm volatile("cp.async.commit_group;" ::: "memory"); \
    } while (0)

#define WAITG(ci, total) do { \
        if ((ci) == (total) - 1) asm volatile("cp.async.wait_group 0;" ::: "memory"); \
        else                     asm volatile("cp.async.wait_group 1;" ::: "memory"); \
    } while (0)

// ---------------------------------------------------------------------------
// Fused LN + GEMM (QKV): M-tile 64; A = LN(gather(x)) resident (3 chunks)
// ---------------------------------------------------------------------------
#define LN_SMEM (3*ACH + 3*BCH + 128)

__global__ void __launch_bounds__(NTH, 2)
gemm_ln(const float* __restrict__ Asrc, const __half* __restrict__ B,
        const float* __restrict__ bias, const float* __restrict__ gamma,
        const float* __restrict__ beta, __half* __restrict__ C, int N)
{
    extern __shared__ char dsm[];
    const uint32_t base  = (smem_u32(dsm) + 127u) & ~127u;
    const uint32_t bBase = base + 3 * ACH;

    DECOMP();
    LDSM_SETUP();
    const long m0 = (long)blockIdx.x * 64;
    const int lm = tid >> 3;
    const int lq = tid & 7;
    const uint32_t bswz = (uint32_t)((lq ^ (lm & 7)) << 4);
    const int NT = N / 192;
    const int total = NT * 3;

    ISSUE_B(0, 0, 0);
    ISSUE_B(1, 0, 1);

    // LN prologue: 8 warps x 8 rows = 64 rows
#pragma unroll 1
    for (int rr = 0; rr < 8; rr++) {
        const int row = wid * 8 + rr;
        const long t = m0 + row;
        const float* src = Asrc + win2orig(t) * Cdim;
        float2 v[3];
        float s = 0.f, ss = 0.f;
#pragma unroll
        for (int i = 0; i < 3; i++) {
            v[i] = *(const float2*)(src + 2 * lane + 64 * i);
            s  += v[i].x + v[i].y;
            ss += v[i].x * v[i].x + v[i].y * v[i].y;
        }
#pragma unroll
        for (int o = 16; o > 0; o >>= 1) {
            s  += __shfl_xor_sync(0xffffffffu, s,  o);
            ss += __shfl_xor_sync(0xffffffffu, ss, o);
        }
        const float mu  = s * (1.f / Cdim);
        const float var = ss * (1.f / Cdim) - mu * mu;
        const float r   = rsqrtf(var + 1e-5f);
        const uint32_t rowaddr = base + (uint32_t)row * 128 +
            ((((uint32_t)lane >> 2) ^ ((uint32_t)row & 7)) << 4) + ((uint32_t)lane & 3) * 4;
#pragma unroll
        for (int i = 0; i < 3; i++) {
            const int c = 2 * lane + 64 * i;
            const float2 gm = *(const float2*)(gamma + c);
            const float2 bt = *(const float2*)(beta + c);
            const __half2 hv = __floats2half2_rn((v[i].x - mu) * r * gm.x + bt.x,
                                                 (v[i].y - mu) * r * gm.y + bt.y);
            sts32(rowaddr + (uint32_t)i * ACH, *(const uint32_t*)&hv);
        }
    }

    float acc[2][6][4];
    CLEAR_ACC();

    for (int ci = 0; ci < total; ci++) {
        const int c = ci % 3;
        WAITG(ci, total);
        __syncthreads();
        if (ci + 2 < total) {
            const int cn = ci + 2;
            ISSUE_B(cn % 3, cn / 3, cn % 3);
        }

        KCHUNK_MMA(base + (uint32_t)c * ACH, bBase + (uint32_t)(ci % 3) * BCH);

        if (c == 2) {
            const int nt = ci / 3;
#pragma unroll
            for (int mi = 0; mi < 2; mi++) {
                const long r0 = m0 + m0w + mi * 16 + g;
                const long r1 = r0 + 8;
#pragma unroll
                for (int ni = 0; ni < 6; ni++) {
                    const int col = nt * 192 + n0w + ni * 8 + 2 * tig;
                    const float b0 = bias[col], b1 = bias[col + 1];
                    *(__half2*)(C + r0 * N + col) =
                        __floats2half2_rn(acc[mi][ni][0] + b0, acc[mi][ni][1] + b1);
                    *(__half2*)(C + r1 * N + col) =
                        __floats2half2_rn(acc[mi][ni][2] + b0, acc[mi][ni][3] + b1);
                    acc[mi][ni][0] = 0.f; acc[mi][ni][1] = 0.f;
                    acc[mi][ni][2] = 0.f; acc[mi][ni][3] = 0.f;
                }
            }
        }
    }
}

// ---------------------------------------------------------------------------
// A-resident fp16 GEMM (FC1): M-tile 64; C = GELU(A @ B^T + bias), half out
// ---------------------------------------------------------------------------
#define HA_SMEM (3*ACH + 3*BCH + 128)

__global__ void __launch_bounds__(NTH, 2)
gemm_ha(const __half* __restrict__ A, const __half* __restrict__ B,
        const float* __restrict__ bias, __half* __restrict__ C, int N)
{
    extern __shared__ char dsm[];
    const uint32_t base  = (smem_u32(dsm) + 127u) & ~127u;
    const uint32_t bBase = base + 3 * ACH;

    DECOMP();
    LDSM_SETUP();
    const long m0 = (long)blockIdx.x * 64;
    const int lm = tid >> 3;
    const int lq = tid & 7;
    const uint32_t bswz = (uint32_t)((lq ^ (lm & 7)) << 4);
    const int NT = N / 192;
    const int total = NT * 3;

    {
        const uint32_t da = base + (uint32_t)lm * 128 + bswz;
        const __half* sa = A + (m0 + lm) * Cdim + lq * 8;
#pragma unroll
        for (int c = 0; c < 3; c++)
#pragma unroll
            for (int it = 0; it < 2; it++)
                cp_async16(da + (uint32_t)c * ACH + it * 4096,
                           sa + (long)it * 32 * Cdim + c * 64);
        asm volatile("cp.async.commit_group;" ::: "memory");
    }

    ISSUE_B(0, 0, 0);
    ISSUE_B(1, 0, 1);

    float acc[2][6][4];
    CLEAR_ACC();

    for (int ci = 0; ci < total; ci++) {
        const int c = ci % 3;
        WAITG(ci, total);
        __syncthreads();
        if (ci + 2 < total) {
            const int cn = ci + 2;
            ISSUE_B(cn % 3, cn / 3, cn % 3);
        }

        KCHUNK_MMA(base + (uint32_t)c * ACH, bBase + (uint32_t)(ci % 3) * BCH);

        if (c == 2) {
            const int nt = ci / 3;
#pragma unroll
            for (int mi = 0; mi < 2; mi++) {
                const long r0 = m0 + m0w + mi * 16 + g;
                const long r1 = r0 + 8;
#pragma unroll
                for (int ni = 0; ni < 6; ni++) {
                    const int col = nt * 192 + n0w + ni * 8 + 2 * tig;
                    const float b0 = bias[col], b1 = bias[col + 1];
                    const float v0 = gelu1(acc[mi][ni][0] + b0);
                    const float v1 = gelu1(acc[mi][ni][1] + b1);
                    const float v2 = gelu1(acc[mi][ni][2] + b0);
                    const float v3 = gelu1(acc[mi][ni][3] + b1);
                    *(__half2*)(C + r0 * N + col) = __floats2half2_rn(v0, v1);
                    *(__half2*)(C + r1 * N + col) = __floats2half2_rn(v2, v3);
                    acc[mi][ni][0] = 0.f; acc[mi][ni][1] = 0.f;
                    acc[mi][ni][2] = 0.f; acc[mi][ni][3] = 0.f;
                }
            }
        }
    }
}

// ---------------------------------------------------------------------------
// Streaming fp16 GEMM, M-tile 64, triple-buffered.
// EPI=2: FC2 (+x1 res -> out fp32). EPI=3: proj (unshift + x res -> x1, LN2 -> ln2)
// ---------------------------------------------------------------------------
#define STAGE  (ACH + BCH)
#define GEMM_SMEM (3*STAGE + 128)

template <int EPI>
__global__ void __launch_bounds__(NTH, 2)
gemm_h(const __half* __restrict__ A, const __half* __restrict__ Bw,
       const float* __restrict__ bias, const float* __restrict__ res,
       float* __restrict__ C, __half* __restrict__ C2,
       const float* __restrict__ gamma, const float* __restrict__ beta,
       int N, int K)
{
    extern __shared__ char dsm[];
    const uint32_t base = (smem_u32(dsm) + 127u) & ~127u;

    DECOMP();
    LDSM_SETUP();
    const long m0 = (long)blockIdx.x * 64;

    const int lm = tid >> 3;
    const int lq = tid & 7;
    const __half* srcA = A + (m0 + lm) * K + lq * 8;
    const __half* srcB = Bw + (long)lm * K + lq * 8;
    const uint32_t swz = (uint32_t)((lq ^ (lm & 7)) << 4);
    const uint32_t dstA0 = base + (uint32_t)lm * 128 + swz;
    const uint32_t dstB0 = base + ACH + (uint32_t)lm * 128 + swz;

    float acc[2][6][4];
    CLEAR_ACC();

    const int NC = K >> 6;

#define ISSUE(buf, kc_) do { \
        const uint32_t so = (uint32_t)(buf) * STAGE; \
        const __half* sa = srcA + (kc_); \
        const __half* sb_ = srcB + (kc_); \
        _Pragma("unroll") \
        for (int it = 0; it < 2; it++) \
            cp_async16(dstA0 + so + it * 4096, sa + (long)it * 32 * K); \
        _Pragma("unroll") \
        for (int it = 0; it < 6; it++) \
            cp_async16(dstB0 + so + it * 4096, sb_ + (long)it * 32 * K); \
        asm volatile("cp.async.commit_group;" ::: "memory"); \
    } while (0)

    ISSUE(0, 0);
    if (NC > 1) ISSUE(1, 64);

    for (int i = 0; i < NC; i++) {
        WAITG(i, NC);
        __syncthreads();
        if (i + 2 < NC) ISSUE((i + 2) % 3, (i + 2) << 6);

        const uint32_t so = (uint32_t)(i % 3) * STAGE;
        KCHUNK_MMA(base + so, base + ACH + so);
    }
#undef ISSUE

#pragma unroll
    for (int mi = 0; mi < 2; mi++) {
        const long rw0 = m0 + m0w + mi * 16 + g;
        const long r0 = (EPI == 3) ? win2orig(rw0) : rw0;
        const long r1 = (EPI == 3) ? win2orig(rw0 + 8) : (rw0 + 8);
#pragma unroll
        for (int ni = 0; ni < 6; ni++) {
            const int col = n0w + ni * 8 + 2 * tig;
            const float b0 = bias[col], b1 = bias[col + 1];
            const float2 ra = *(const float2*)(res + r0 * N + col);
            const float2 rb = *(const float2*)(res + r1 * N + col);
            acc[mi][ni][0] += b0 + ra.x;
            acc[mi][ni][1] += b1 + ra.y;
            acc[mi][ni][2] += b0 + rb.x;
            acc[mi][ni][3] += b1 + rb.y;
        }
    }

    if (EPI == 3) {
        float* rsum   = (float*)(dsm);
        float* rsumsq = rsum + 64;
        __syncthreads();
        if (tid < 64) { rsum[tid] = 0.f; rsumsq[tid] = 0.f; }
        __syncthreads();
#pragma unroll
        for (int mi = 0; mi < 2; mi++) {
            const int row0 = m0w + mi * 16 + g;
            float s0 = 0.f, q0 = 0.f, s1 = 0.f, q1 = 0.f;
#pragma unroll
            for (int ni = 0; ni < 6; ni++) {
                s0 += acc[mi][ni][0] + acc[mi][ni][1];
                q0 += acc[mi][ni][0] * acc[mi][ni][0] + acc[mi][ni][1] * acc[mi][ni][1];
                s1 += acc[mi][ni][2] + acc[mi][ni][3];
                q1 += acc[mi][ni][2] * acc[mi][ni][2] + acc[mi][ni][3] * acc[mi][ni][3];
            }
            atomicAdd(&rsum[row0], s0);     atomicAdd(&rsumsq[row0], q0);
            atomicAdd(&rsum[row0 + 8], s1); atomicAdd(&rsumsq[row0 + 8], q1);
        }
        __syncthreads();
    }

#pragma unroll
    for (int mi = 0; mi < 2; mi++) {
        const long rw0 = m0 + m0w + mi * 16 + g;
        const long r0 = (EPI == 3) ? win2orig(rw0) : rw0;
        const long r1 = (EPI == 3) ? win2orig(rw0 + 8) : (rw0 + 8);

        float mu0 = 0.f, rs0 = 0.f, mu1 = 0.f, rs1 = 0.f;
        if (EPI == 3) {
            const float* rsum   = (const float*)(dsm);
            const float* rsumsq = rsum + 64;
            const int row0 = m0w + mi * 16 + g;
            mu0 = rsum[row0] * (1.f / Cdim);
            rs0 = rsqrtf(rsumsq[row0] * (1.f / Cdim) - mu0 * mu0 + 1e-5f);
            mu1 = rsum[row0 + 8] * (1.f / Cdim);
            rs1 = rsqrtf(rsumsq[row0 + 8] * (1.f / Cdim) - mu1 * mu1 + 1e-5f);
        }
#pragma unroll
        for (int ni = 0; ni < 6; ni++) {
            const int col = n0w + ni * 8 + 2 * tig;
            const float v0 = acc[mi][ni][0], v1 = acc[mi][ni][1];
            const float v2 = acc[mi][ni][2], v3 = acc[mi][ni][3];
            *(float2*)(C + r0 * N + col) = make_float2(v0, v1);
            *(float2*)(C + r1 * N + col) = make_float2(v2, v3);
            if (EPI == 3) {
                const float2 gm = *(const float2*)(gamma + col);
                const float2 bt = *(const float2*)(beta + col);
                *(__half2*)(C2 + r0 * N + col) = __floats2half2_rn(
                    (v0 - mu0) * rs0 * gm.x + bt.x, (v1 - mu0) * rs0 * gm.y + bt.y);
                *(__half2*)(C2 + r1 * N + col) = __floats2half2_rn(
                    (v2 - mu1) * rs1 * gm.x + bt.x, (v3 - mu1) * rs1 * gm.y + bt.y);
            }
        }
    }
}

// ---------------------------------------------------------------------------
// One-shot weight conversion fp32 -> fp16 (4 tensors)
// ---------------------------------------------------------------------------
__global__ void tohalf_all(const float* __restrict__ s0, const float* __restrict__ s1,
                           const float* __restrict__ s2, const float* __restrict__ s3,
                           __half* __restrict__ dst)
{
    const int i = blockIdx.x * 1024 + threadIdx.x * 4;
    const float* src;
    int off;
    if (i < 110592)      { src = s0; off = 0; }
    else if (i < 147456) { src = s1; off = 110592; }
    else if (i < 294912) { src = s2; off = 147456; }
    else                 { src = s3; off = 294912; }
    const float4 v = *(const float4*)(src + (i - off));
    __half2* d = (__half2*)(dst + i);
    d[0] = __floats2half2_rn(v.x, v.y);
    d[1] = __floats2half2_rn(v.z, v.w);
}

// ---------------------------------------------------------------------------
// Fused window attention v3. Block per (window, head), 64 threads.
// All global/shared q,k,v traffic via 16B vectors; identical arithmetic to v2.
// ---------------------------------------------------------------------------
__global__ void __launch_bounds__(64, 16)
attn_kernel(const __half* __restrict__ qkv,
            const float* __restrict__ rpb,
            __half* __restrict__ out)
{
    const int win  = blockIdx.x;
    const int head = blockIdx.y;
    const int n    = threadIdx.x;

    __shared__ __half2 ks[64][20];   // 80B rows (16B-aligned)
    __shared__ __half2 vs[64][20];
    __shared__ __half  sp[64][66];
    __shared__ float   sbias[225];
    __shared__ int     lab[64];

    const __half* base = qkv + (long)win * NPW * (3 * Cdim);
    {
        const uint4* kg = (const uint4*)(base + n * (3 * Cdim) + Cdim + head * HD);
        const uint4* vg = (const uint4*)(base + n * (3 * Cdim) + 2 * Cdim + head * HD);
        uint4* kd = (uint4*)&ks[n][0];
        uint4* vd = (uint4*)&vs[n][0];
#pragma unroll
        for (int t = 0; t < 4; t++) { kd[t] = kg[t]; vd[t] = vg[t]; }
    }
    for (int idx = n; idx < 225; idx += 64) sbias[idx] = rpb[idx * NH + head];
    {
        const int wi = win & 255;
        const int gh = (wi >> 4) * 8 + (n >> 3);
        const int gw = (wi & 15) * 8 + (n & 7);
        const int rh = (gh < Himg - WS) ? 0 : ((gh < Himg - SHIFT) ? 1 : 2);
        const int rw = (gw < Wimg - WS) ? 0 : ((gw < Wimg - SHIFT) ? 1 : 2);
        lab[n] = rh * 3 + rw;
    }
    __syncthreads();

    float q[HD];
    {
        const uint4* qg = (const uint4*)(base + n * (3 * Cdim) + head * HD);
#pragma unroll
        for (int t = 0; t < 4; t++) {
            const uint4 u = qg[t];
            const __half2* h2 = (const __half2*)&u;
#pragma unroll
            for (int p = 0; p < 4; p++) {
                const float2 f = __half22float2(h2[p]);
                q[t * 8 + 2 * p]     = f.x * 0.17677669529663687f;
                q[t * 8 + 2 * p + 1] = f.y * 0.17677669529663687f;
            }
        }
    }

    const int i = n >> 3, j = n & 7;
    const int myl = lab[n];

    float sc[64];
    float mx = -1e30f;
#pragma unroll 4
    for (int m = 0; m < 64; m++) {
        const uint4* kr = (const uint4*)&ks[m][0];
        float s = 0.f;
#pragma unroll
        for (int t = 0; t < 4; t++) {
            const uint4 u = kr[t];
            const __half2* h2 = (const __half2*)&u;
#pragma unroll
            for (int p = 0; p < 4; p++) {
                const float2 kv = __half22float2(h2[p]);
                s += q[t * 8 + 2 * p] * kv.x + q[t * 8 + 2 * p + 1] * kv.y;
            }
        }
        s += sbias[(i - (m >> 3) + 7) * 15 + (j - (m & 7) + 7)];
        if (lab[m] != myl) s -= 100.f;
        sc[m] = s;
        mx = fmaxf(mx, s);
    }
    float sum = 0.f;
#pragma unroll 4
    for (int m = 0; m < 64; m++) {
        const float e = __expf(sc[m] - mx);
        sc[m] = e;
        sum += e;
    }
    const float inv = __fdividef(1.f, sum);
#pragma unroll 4
    for (int m = 0; m < 64; m++)
        sp[n][m] = __float2half_rn(sc[m] * inv);
    __syncwarp();

    float accv[HD];
#pragma unroll
    for (int d = 0; d < HD; d++) accv[d] = 0.f;
#pragma unroll 2
    for (int m = 0; m < 64; m++) {
        const float p = __half2float(sp[n][m]);
        const uint4* vr = (const uint4*)&vs[m][0];
#pragma unroll
        for (int t = 0; t < 4; t++) {
            const uint4 u = vr[t];
            const __half2* h2 = (const __half2*)&u;
#pragma unroll
            for (int pp = 0; pp < 4; pp++) {
                const float2 vv = __half22float2(h2[pp]);
                accv[t * 8 + 2 * pp]     += p * vv.x;
                accv[t * 8 + 2 * pp + 1] += p * vv.y;
            }
        }
    }

    // pack + 16B stores
    {
        __half2 ph[16];
#pragma unroll
        for (int dp = 0; dp < 16; dp++)
            ph[dp] = __floats2half2_rn(accv[2 * dp], accv[2 * dp + 1]);
        uint4* dst4 = (uint4*)(out + ((long)win * NPW + n) * Cdim + head * HD);
        const uint4* src4 = (const uint4*)ph;
#pragma unroll
        for (int t = 0; t < 4; t++) dst4[t] = src4[t];
    }
}

// ---------------------------------------------------------------------------
// Launch
// ---------------------------------------------------------------------------
extern "C" void kernel_launch(void* const* d_in, const int* in_sizes, int n_in,
                              void* d_out, int out_size)
{
    const float* x      = (const float*)d_in[0];
    const float* g1     = (const float*)d_in[1];
    const float* b1     = (const float*)d_in[2];
    const float* qkv_w  = (const float*)d_in[3];
    const float* qkv_b  = (const float*)d_in[4];
    const float* rpb    = (const float*)d_in[5];
    const float* proj_w = (const float*)d_in[6];
    const float* proj_b = (const float*)d_in[7];
    const float* g2     = (const float*)d_in[8];
    const float* b2     = (const float*)d_in[9];
    const float* fc1_w  = (const float*)d_in[10];
    const float* fc1_b  = (const float*)d_in[11];
    const float* fc2_w  = (const float*)d_in[12];
    const float* fc2_b  = (const float*)d_in[13];
    float* out = (float*)d_out;

    __half *p_qkv, *p_att, *p_ln2, *p_hh, *p_wh;
    float *p_x1;
    cudaGetSymbolAddress((void**)&p_qkv, g_qkv);
    cudaGetSymbolAddress((void**)&p_att, g_att);
    cudaGetSymbolAddress((void**)&p_ln2, g_ln2);
    cudaGetSymbolAddress((void**)&p_hh,  g_hh);
    cudaGetSymbolAddress((void**)&p_x1,  g_x1);
    cudaGetSymbolAddress((void**)&p_wh,  g_wh);

    static bool attr_set = false;
    if (!attr_set) {
        cudaFuncSetAttribute(gemm_ln,   cudaFuncAttributeMaxDynamicSharedMemorySize, LN_SMEM);
        cudaFuncSetAttribute(gemm_ha,   cudaFuncAttributeMaxDynamicSharedMemorySize, HA_SMEM);
        cudaFuncSetAttribute(gemm_h<3>, cudaFuncAttributeMaxDynamicSharedMemorySize, GEMM_SMEM);
        cudaFuncSetAttribute(gemm_h<2>, cudaFuncAttributeMaxDynamicSharedMemorySize, GEMM_SMEM);
        attr_set = true;
    }

    __half* w_qkv = p_wh;
    __half* w_prj = p_wh + 110592;
    __half* w_fc1 = p_wh + 147456;
    __half* w_fc2 = p_wh + 294912;

    // 0. weights fp32 -> fp16
    tohalf_all<<<442368 / 1024, 256>>>(qkv_w, proj_w, fc1_w, fc2_w, p_wh);

    const int M = NTOK;  // 131072, 2048 M-tiles of 64

    // 1. QKV (fused LN1 + shift/window gather)
    gemm_ln<<<M / 64, NTH, LN_SMEM>>>(x, w_qkv, qkv_b, g1, b1, p_qkv, 3 * Cdim);

    // 2. Window attention
    attn_kernel<<<dim3(NWIN, NH), 64>>>(p_qkv, rpb, p_att);

    // 3. proj + unshift + x residual -> x1 fp32; fused LN2 -> ln2 fp16
    gemm_h<3><<<M / 64, NTH, GEMM_SMEM>>>(
        p_att, w_prj, proj_b, x, p_x1, p_ln2, g2, b2, Cdim, Cdim);

    // 4. FC1 + GELU (A-resident)
    gemm_ha<<<M / 64, NTH, HA_SMEM>>>(p_ln2, w_fc1, fc1_b, p_hh, HID);

    // 5. FC2 + x1 residual -> out fp32
    gemm_h<2><<<M / 64, NTH, GEMM_SMEM>>>(
        p_hh, w_fc2, fc2_b, p_x1, out, nullptr, nullptr, nullptr, Cdim, HID);
}

// round 16
// speedup vs baseline: 1.5358x; 1.3676x over previous
#include <cuda_runtime.h>
#include <cuda_fp16.h>
#include <math.h>
#include <stdint.h>

// ---------------------------------------------------------------------------
// Problem constants
// ---------------------------------------------------------------------------
#define Bsz   8
#define Himg  128
#define Wimg  128
#define Cdim  192
#define HID   768
#define WS    8
#define SHIFT 4
#define NH    6
#define HD    32
#define NTOK  (Bsz*Himg*Wimg)             // 131072
#define NWIN  2048
#define NPW   64

// ---------------------------------------------------------------------------
// Scratch
// ---------------------------------------------------------------------------
__device__ __align__(16) __half g_qkv[(size_t)NTOK * 3 * Cdim];
__device__ __align__(16) __half g_att[(size_t)NTOK * Cdim];
__device__ __align__(16) __half g_ln2[(size_t)NTOK * Cdim];
__device__ __align__(16) __half g_hh [(size_t)NTOK * HID];
__device__ __align__(16) float  g_x1 [(size_t)NTOK * Cdim];
__device__ __align__(16) __half g_wh[442368];   // qkv@0 proj@110592 fc1@147456 fc2@294912

// ---------------------------------------------------------------------------
// Helpers
// ---------------------------------------------------------------------------
__device__ __forceinline__ uint32_t smem_u32(const void* p) {
    uint32_t a;
    asm("{ .reg .u64 t; cvta.to.shared.u64 t, %1; cvt.u32.u64 %0, t; }" : "=r"(a) : "l"(p));
    return a;
}
__device__ __forceinline__ void cp_async16(uint32_t dst, const void* src) {
    asm volatile("cp.async.cg.shared.global [%0], [%1], 16;" :: "r"(dst), "l"(src) : "memory");
}
__device__ __forceinline__ void sts32(uint32_t addr, uint32_t v) {
    asm volatile("st.shared.b32 [%0], %1;" :: "r"(addr), "r"(v) : "memory");
}
__device__ __forceinline__ void ldsm4(uint32_t* r, uint32_t addr) {
    asm volatile("ldmatrix.sync.aligned.m8n8.x4.shared.b16 {%0,%1,%2,%3}, [%4];"
        : "=r"(r[0]), "=r"(r[1]), "=r"(r[2]), "=r"(r[3]) : "r"(addr));
}
__device__ __forceinline__ void ldsm4t(uint32_t* r, uint32_t addr) {
    asm volatile("ldmatrix.sync.aligned.m8n8.x4.trans.shared.b16 {%0,%1,%2,%3}, [%4];"
        : "=r"(r[0]), "=r"(r[1]), "=r"(r[2]), "=r"(r[3]) : "r"(addr));
}
__device__ __forceinline__ void mma16(float* c, const uint32_t* a, const uint32_t* b) {
    asm volatile("mma.sync.aligned.m16n8k16.row.col.f32.f16.f16.f32 "
        "{%0,%1,%2,%3}, {%4,%5,%6,%7}, {%8,%9}, {%0,%1,%2,%3};"
        : "+f"(c[0]), "+f"(c[1]), "+f"(c[2]), "+f"(c[3])
        : "r"(a[0]), "r"(a[1]), "r"(a[2]), "r"(a[3]), "r"(b[0]), "r"(b[1]));
}
__device__ __forceinline__ long win2orig(long t) {
    const int b_ = (int)(t >> 6), n = (int)(t & 63);
    const int b = b_ >> 8, wi = b_ & 255;
    const int h = ((wi >> 4) * 8 + (n >> 3) + SHIFT) & 127;
    const int w = ((wi & 15) * 8 + (n & 7) + SHIFT) & 127;
    return ((long)b * 128 + h) * 128 + w;
}
// Branchless GELU: Abramowitz-Stegun 7.1.26 erf approx (|err| < 1.5e-7)
__device__ __forceinline__ float gelu1(float x) {
    const float z  = 0.7071067811865475f * x;
    const float az = fabsf(z);
    const float t  = __fdividef(1.f, 1.f + 0.3275911f * az);
    float p = 1.061405429f;
    p = p * t - 1.453152027f;
    p = p * t + 1.421413741f;
    p = p * t - 0.284496736f;
    p = p * t + 0.254829592f;
    p = p * t;
    const float e  = __expf(-z * z);
    float er = 1.f - p * e;
    er = copysignf(er, z);
    return 0.5f * x * (1.f + er);
}

#define ACH 8192       // 64 rows x 128B
#define BCH 24576      // 192 rows x 128B
#define NTH 256

// 8 warps: 2m x 4n, warp tile 32x48, M-tile 64
#define DECOMP() \
    const int tid  = threadIdx.x; \
    const int wid  = tid >> 5; \
    const int lane = tid & 31; \
    const int g    = lane >> 2; \
    const int tig  = lane & 3; \
    const int m0w  = (wid >> 2) * 32; \
    const int n0w  = (wid & 3) * 48;

#define LDSM_SETUP() \
    const int l8 = lane & 7; \
    const int aHi = lane >> 4; \
    const uint32_t aOff0 = (uint32_t)(m0w + l8 + ((lane >> 3) & 1) * 8) * 128; \
    const int bHi = (lane >> 3) & 1; \
    const uint32_t bOff0 = (uint32_t)(n0w + l8 + ((lane >> 4) & 1) * 8) * 128;

#define KCHUNK_MMA(aB, bB) \
    _Pragma("unroll") \
    for (int s = 0; s < 4; s++) { \
        const uint32_t ac = (uint32_t)(((2 * s + aHi) ^ l8) << 4); \
        const uint32_t bc = (uint32_t)(((2 * s + bHi) ^ l8) << 4); \
        uint32_t af[2][4], bp[3][4]; \
        _Pragma("unroll") \
        for (int mi = 0; mi < 2; mi++) ldsm4(af[mi], (aB) + aOff0 + mi * 2048 + ac); \
        _Pragma("unroll") \
        for (int p = 0; p < 3; p++)  ldsm4(bp[p], (bB) + bOff0 + p * 2048 + bc); \
        _Pragma("unroll") \
        for (int mi = 0; mi < 2; mi++) \
            _Pragma("unroll") \
            for (int ni = 0; ni < 6; ni++) \
                mma16(acc[mi][ni], af[mi], &bp[ni >> 1][(ni & 1) * 2]); \
    }

#define CLEAR_ACC() \
    _Pragma("unroll") \
    for (int mi = 0; mi < 2; mi++) \
        _Pragma("unroll") \
        for (int ni = 0; ni < 6; ni++) \
            _Pragma("unroll") \
            for (int c = 0; c < 4; c++) acc[mi][ni][c] = 0.f;

// B chunk loader: 192 rows, 256 threads -> 6 iterations of 32 rows. buf in {0,1,2}
#define ISSUE_B(buf, nt, c) do { \
        const uint32_t bd = bBase + (uint32_t)(buf) * BCH + (uint32_t)lm * 128 + bswz; \
        const __half* sb_ = B + ((long)(nt) * 192 + lm) * Cdim + (c) * 64 + lq * 8; \
        _Pragma("unroll") \
        for (int it = 0; it < 6; it++) \
            cp_async16(bd + it * 4096, sb_ + (long)it * 32 * Cdim); \
        asm volatile("cp.async.commit_group;" ::: "memory"); \
    } while (0)

#define WAITG(ci, total) do { \
        if ((ci) == (total) - 1) asm volatile("cp.async.wait_group 0;" ::: "memory"); \
        else                     asm volatile("cp.async.wait_group 1;" ::: "memory"); \
    } while (0)

// ---------------------------------------------------------------------------
// Fused LN + GEMM (QKV): M-tile 64; A = LN(gather(x)) resident (3 chunks)
// ---------------------------------------------------------------------------
#define LN_SMEM (3*ACH + 3*BCH + 128)

__global__ void __launch_bounds__(NTH, 2)
gemm_ln(const float* __restrict__ Asrc, const __half* __restrict__ B,
        const float* __restrict__ bias, const float* __restrict__ gamma,
        const float* __restrict__ beta, __half* __restrict__ C, int N)
{
    extern __shared__ char dsm[];
    const uint32_t base  = (smem_u32(dsm) + 127u) & ~127u;
    const uint32_t bBase = base + 3 * ACH;

    DECOMP();
    LDSM_SETUP();
    const long m0 = (long)blockIdx.x * 64;
    const int lm = tid >> 3;
    const int lq = tid & 7;
    const uint32_t bswz = (uint32_t)((lq ^ (lm & 7)) << 4);
    const int NT = N / 192;
    const int total = NT * 3;

    ISSUE_B(0, 0, 0);
    ISSUE_B(1, 0, 1);

    // LN prologue: 8 warps x 8 rows = 64 rows
#pragma unroll 1
    for (int rr = 0; rr < 8; rr++) {
        const int row = wid * 8 + rr;
        const long t = m0 + row;
        const float* src = Asrc + win2orig(t) * Cdim;
        float2 v[3];
        float s = 0.f, ss = 0.f;
#pragma unroll
        for (int i = 0; i < 3; i++) {
            v[i] = *(const float2*)(src + 2 * lane + 64 * i);
            s  += v[i].x + v[i].y;
            ss += v[i].x * v[i].x + v[i].y * v[i].y;
        }
#pragma unroll
        for (int o = 16; o > 0; o >>= 1) {
            s  += __shfl_xor_sync(0xffffffffu, s,  o);
            ss += __shfl_xor_sync(0xffffffffu, ss, o);
        }
        const float mu  = s * (1.f / Cdim);
        const float var = ss * (1.f / Cdim) - mu * mu;
        const float r   = rsqrtf(var + 1e-5f);
        const uint32_t rowaddr = base + (uint32_t)row * 128 +
            ((((uint32_t)lane >> 2) ^ ((uint32_t)row & 7)) << 4) + ((uint32_t)lane & 3) * 4;
#pragma unroll
        for (int i = 0; i < 3; i++) {
            const int c = 2 * lane + 64 * i;
            const float2 gm = *(const float2*)(gamma + c);
            const float2 bt = *(const float2*)(beta + c);
            const __half2 hv = __floats2half2_rn((v[i].x - mu) * r * gm.x + bt.x,
                                                 (v[i].y - mu) * r * gm.y + bt.y);
            sts32(rowaddr + (uint32_t)i * ACH, *(const uint32_t*)&hv);
        }
    }

    float acc[2][6][4];
    CLEAR_ACC();

    for (int ci = 0; ci < total; ci++) {
        const int c = ci % 3;
        WAITG(ci, total);
        __syncthreads();
        if (ci + 2 < total) {
            const int cn = ci + 2;
            ISSUE_B(cn % 3, cn / 3, cn % 3);
        }

        KCHUNK_MMA(base + (uint32_t)c * ACH, bBase + (uint32_t)(ci % 3) * BCH);

        if (c == 2) {
            const int nt = ci / 3;
#pragma unroll
            for (int mi = 0; mi < 2; mi++) {
                const long r0 = m0 + m0w + mi * 16 + g;
                const long r1 = r0 + 8;
#pragma unroll
                for (int ni = 0; ni < 6; ni++) {
                    const int col = nt * 192 + n0w + ni * 8 + 2 * tig;
                    const float b0 = bias[col], b1 = bias[col + 1];
                    *(__half2*)(C + r0 * N + col) =
                        __floats2half2_rn(acc[mi][ni][0] + b0, acc[mi][ni][1] + b1);
                    *(__half2*)(C + r1 * N + col) =
                        __floats2half2_rn(acc[mi][ni][2] + b0, acc[mi][ni][3] + b1);
                    acc[mi][ni][0] = 0.f; acc[mi][ni][1] = 0.f;
                    acc[mi][ni][2] = 0.f; acc[mi][ni][3] = 0.f;
                }
            }
        }
    }
}

// ---------------------------------------------------------------------------
// A-resident fp16 GEMM (FC1): M-tile 64; C = GELU(A @ B^T + bias), half out
// ---------------------------------------------------------------------------
#define HA_SMEM (3*ACH + 3*BCH + 128)

__global__ void __launch_bounds__(NTH, 2)
gemm_ha(const __half* __restrict__ A, const __half* __restrict__ B,
        const float* __restrict__ bias, __half* __restrict__ C, int N)
{
    extern __shared__ char dsm[];
    const uint32_t base  = (smem_u32(dsm) + 127u) & ~127u;
    const uint32_t bBase = base + 3 * ACH;

    DECOMP();
    LDSM_SETUP();
    const long m0 = (long)blockIdx.x * 64;
    const int lm = tid >> 3;
    const int lq = tid & 7;
    const uint32_t bswz = (uint32_t)((lq ^ (lm & 7)) << 4);
    const int NT = N / 192;
    const int total = NT * 3;

    {
        const uint32_t da = base + (uint32_t)lm * 128 + bswz;
        const __half* sa = A + (m0 + lm) * Cdim + lq * 8;
#pragma unroll
        for (int c = 0; c < 3; c++)
#pragma unroll
            for (int it = 0; it < 2; it++)
                cp_async16(da + (uint32_t)c * ACH + it * 4096,
                           sa + (long)it * 32 * Cdim + c * 64);
        asm volatile("cp.async.commit_group;" ::: "memory");
    }

    ISSUE_B(0, 0, 0);
    ISSUE_B(1, 0, 1);

    float acc[2][6][4];
    CLEAR_ACC();

    for (int ci = 0; ci < total; ci++) {
        const int c = ci % 3;
        WAITG(ci, total);
        __syncthreads();
        if (ci + 2 < total) {
            const int cn = ci + 2;
            ISSUE_B(cn % 3, cn / 3, cn % 3);
        }

        KCHUNK_MMA(base + (uint32_t)c * ACH, bBase + (uint32_t)(ci % 3) * BCH);

        if (c == 2) {
            const int nt = ci / 3;
#pragma unroll
            for (int mi = 0; mi < 2; mi++) {
                const long r0 = m0 + m0w + mi * 16 + g;
                const long r1 = r0 + 8;
#pragma unroll
                for (int ni = 0; ni < 6; ni++) {
                    const int col = nt * 192 + n0w + ni * 8 + 2 * tig;
                    const float b0 = bias[col], b1 = bias[col + 1];
                    const float v0 = gelu1(acc[mi][ni][0] + b0);
                    const float v1 = gelu1(acc[mi][ni][1] + b1);
                    const float v2 = gelu1(acc[mi][ni][2] + b0);
                    const float v3 = gelu1(acc[mi][ni][3] + b1);
                    *(__half2*)(C + r0 * N + col) = __floats2half2_rn(v0, v1);
                    *(__half2*)(C + r1 * N + col) = __floats2half2_rn(v2, v3);
                    acc[mi][ni][0] = 0.f; acc[mi][ni][1] = 0.f;
                    acc[mi][ni][2] = 0.f; acc[mi][ni][3] = 0.f;
                }
            }
        }
    }
}

// ---------------------------------------------------------------------------
// Streaming fp16 GEMM, M-tile 64, triple-buffered.
// EPI=2: FC2 (+x1 res -> out fp32). EPI=3: proj (unshift + x res -> x1, LN2 -> ln2)
// ---------------------------------------------------------------------------
#define STAGE  (ACH + BCH)
#define GEMM_SMEM (3*STAGE + 128)

template <int EPI>
__global__ void __launch_bounds__(NTH, 2)
gemm_h(const __half* __restrict__ A, const __half* __restrict__ Bw,
       const float* __restrict__ bias, const float* __restrict__ res,
       float* __restrict__ C, __half* __restrict__ C2,
       const float* __restrict__ gamma, const float* __restrict__ beta,
       int N, int K)
{
    extern __shared__ char dsm[];
    const uint32_t base = (smem_u32(dsm) + 127u) & ~127u;

    DECOMP();
    LDSM_SETUP();
    const long m0 = (long)blockIdx.x * 64;

    const int lm = tid >> 3;
    const int lq = tid & 7;
    const __half* srcA = A + (m0 + lm) * K + lq * 8;
    const __half* srcB = Bw + (long)lm * K + lq * 8;
    const uint32_t swz = (uint32_t)((lq ^ (lm & 7)) << 4);
    const uint32_t dstA0 = base + (uint32_t)lm * 128 + swz;
    const uint32_t dstB0 = base + ACH + (uint32_t)lm * 128 + swz;

    float acc[2][6][4];
    CLEAR_ACC();

    const int NC = K >> 6;

#define ISSUE(buf, kc_) do { \
        const uint32_t so = (uint32_t)(buf) * STAGE; \
        const __half* sa = srcA + (kc_); \
        const __half* sb_ = srcB + (kc_); \
        _Pragma("unroll") \
        for (int it = 0; it < 2; it++) \
            cp_async16(dstA0 + so + it * 4096, sa + (long)it * 32 * K); \
        _Pragma("unroll") \
        for (int it = 0; it < 6; it++) \
            cp_async16(dstB0 + so + it * 4096, sb_ + (long)it * 32 * K); \
        asm volatile("cp.async.commit_group;" ::: "memory"); \
    } while (0)

    ISSUE(0, 0);
    if (NC > 1) ISSUE(1, 64);

    for (int i = 0; i < NC; i++) {
        WAITG(i, NC);
        __syncthreads();
        if (i + 2 < NC) ISSUE((i + 2) % 3, (i + 2) << 6);

        const uint32_t so = (uint32_t)(i % 3) * STAGE;
        KCHUNK_MMA(base + so, base + ACH + so);
    }
#undef ISSUE

#pragma unroll
    for (int mi = 0; mi < 2; mi++) {
        const long rw0 = m0 + m0w + mi * 16 + g;
        const long r0 = (EPI == 3) ? win2orig(rw0) : rw0;
        const long r1 = (EPI == 3) ? win2orig(rw0 + 8) : (rw0 + 8);
#pragma unroll
        for (int ni = 0; ni < 6; ni++) {
            const int col = n0w + ni * 8 + 2 * tig;
            const float b0 = bias[col], b1 = bias[col + 1];
            const float2 ra = *(const float2*)(res + r0 * N + col);
            const float2 rb = *(const float2*)(res + r1 * N + col);
            acc[mi][ni][0] += b0 + ra.x;
            acc[mi][ni][1] += b1 + ra.y;
            acc[mi][ni][2] += b0 + rb.x;
            acc[mi][ni][3] += b1 + rb.y;
        }
    }

    if (EPI == 3) {
        float* rsum   = (float*)(dsm);
        float* rsumsq = rsum + 64;
        __syncthreads();
        if (tid < 64) { rsum[tid] = 0.f; rsumsq[tid] = 0.f; }
        __syncthreads();
#pragma unroll
        for (int mi = 0; mi < 2; mi++) {
            const int row0 = m0w + mi * 16 + g;
            float s0 = 0.f, q0 = 0.f, s1 = 0.f, q1 = 0.f;
#pragma unroll
            for (int ni = 0; ni < 6; ni++) {
                s0 += acc[mi][ni][0] + acc[mi][ni][1];
                q0 += acc[mi][ni][0] * acc[mi][ni][0] + acc[mi][ni][1] * acc[mi][ni][1];
                s1 += acc[mi][ni][2] + acc[mi][ni][3];
                q1 += acc[mi][ni][2] * acc[mi][ni][2] + acc[mi][ni][3] * acc[mi][ni][3];
            }
            atomicAdd(&rsum[row0], s0);     atomicAdd(&rsumsq[row0], q0);
            atomicAdd(&rsum[row0 + 8], s1); atomicAdd(&rsumsq[row0 + 8], q1);
        }
        __syncthreads();
    }

#pragma unroll
    for (int mi = 0; mi < 2; mi++) {
        const long rw0 = m0 + m0w + mi * 16 + g;
        const long r0 = (EPI == 3) ? win2orig(rw0) : rw0;
        const long r1 = (EPI == 3) ? win2orig(rw0 + 8) : (rw0 + 8);

        float mu0 = 0.f, rs0 = 0.f, mu1 = 0.f, rs1 = 0.f;
        if (EPI == 3) {
            const float* rsum   = (const float*)(dsm);
            const float* rsumsq = rsum + 64;
            const int row0 = m0w + mi * 16 + g;
            mu0 = rsum[row0] * (1.f / Cdim);
            rs0 = rsqrtf(rsumsq[row0] * (1.f / Cdim) - mu0 * mu0 + 1e-5f);
            mu1 = rsum[row0 + 8] * (1.f / Cdim);
            rs1 = rsqrtf(rsumsq[row0 + 8] * (1.f / Cdim) - mu1 * mu1 + 1e-5f);
        }
#pragma unroll
        for (int ni = 0; ni < 6; ni++) {
            const int col = n0w + ni * 8 + 2 * tig;
            const float v0 = acc[mi][ni][0], v1 = acc[mi][ni][1];
            const float v2 = acc[mi][ni][2], v3 = acc[mi][ni][3];
            *(float2*)(C + r0 * N + col) = make_float2(v0, v1);
            *(float2*)(C + r1 * N + col) = make_float2(v2, v3);
            if (EPI == 3) {
                const float2 gm = *(const float2*)(gamma + col);
                const float2 bt = *(const float2*)(beta + col);
                *(__half2*)(C2 + r0 * N + col) = __floats2half2_rn(
                    (v0 - mu0) * rs0 * gm.x + bt.x, (v1 - mu0) * rs0 * gm.y + bt.y);
                *(__half2*)(C2 + r1 * N + col) = __floats2half2_rn(
                    (v2 - mu1) * rs1 * gm.x + bt.x, (v3 - mu1) * rs1 * gm.y + bt.y);
            }
        }
    }
}

// ---------------------------------------------------------------------------
// One-shot weight conversion fp32 -> fp16 (4 tensors)
// ---------------------------------------------------------------------------
__global__ void tohalf_all(const float* __restrict__ s0, const float* __restrict__ s1,
                           const float* __restrict__ s2, const float* __restrict__ s3,
                           __half* __restrict__ dst)
{
    const int i = blockIdx.x * 1024 + threadIdx.x * 4;
    const float* src;
    int off;
    if (i < 110592)      { src = s0; off = 0; }
    else if (i < 147456) { src = s1; off = 110592; }
    else if (i < 294912) { src = s2; off = 147456; }
    else                 { src = s3; off = 294912; }
    const float4 v = *(const float4*)(src + (i - off));
    __half2* d = (__half2*)(dst + i);
    d[0] = __floats2half2_rn(v.x, v.y);
    d[1] = __floats2half2_rn(v.z, v.w);
}

// ---------------------------------------------------------------------------
// Fused window attention v4: mma.sync. Block=(window, head), 64 threads (2 warps).
// Each warp: 32 query rows as two m16 strips. S=QK^T and PV on tensor pipe.
// ---------------------------------------------------------------------------
__global__ void __launch_bounds__(64, 8)
attn_kernel(const __half* __restrict__ qkv,
            const float* __restrict__ rpb,
            __half* __restrict__ out)
{
    const int win  = blockIdx.x;
    const int head = blockIdx.y;
    const int tid  = threadIdx.x;
    const int w    = tid >> 5;
    const int lane = tid & 31;
    const int g    = lane >> 2;
    const int tig  = lane & 3;

    __shared__ __half qs[64 * 40];   // 80B rows
    __shared__ __half ks[64 * 40];
    __shared__ __half vs[64 * 40];
    __shared__ float  sbias[225];
    __shared__ int    lab[64];

    const __half* base = qkv + (long)win * NPW * 576;
    {
        const uint4* qg = (const uint4*)(base + tid * 576 + head * HD);
        const uint4* kg = (const uint4*)(base + tid * 576 + 192 + head * HD);
        const uint4* vg = (const uint4*)(base + tid * 576 + 384 + head * HD);
        uint4* qd = (uint4*)(qs + tid * 40);
        uint4* kd = (uint4*)(ks + tid * 40);
        uint4* vd = (uint4*)(vs + tid * 40);
#pragma unroll
        for (int t = 0; t < 4; t++) { qd[t] = qg[t]; kd[t] = kg[t]; vd[t] = vg[t]; }
    }
    for (int idx = tid; idx < 225; idx += 64) sbias[idx] = rpb[idx * NH + head];
    {
        const int wi = win & 255;
        const int gh = (wi >> 4) * 8 + (tid >> 3);
        const int gw = (wi & 15) * 8 + (tid & 7);
        const int rh = (gh < Himg - WS) ? 0 : ((gh < Himg - SHIFT) ? 1 : 2);
        const int rw = (gw < Wimg - WS) ? 0 : ((gw < Wimg - SHIFT) ? 1 : 2);
        lab[tid] = rh * 3 + rw;
    }
    __syncthreads();

    const uint32_t qsb = smem_u32(qs);
    const uint32_t ksb = smem_u32(ks);
    const uint32_t vsb = smem_u32(vs);
    const int l7 = lane & 7;
    // A-frag (Q / P): mats {r0-7 klo, r8-15 klo, r0-7 khi, r8-15 khi}
    const uint32_t aRow = (uint32_t)(l7 + ((lane >> 3) & 1) * 8) * 80 + ((lane >> 4) & 1) * 16;
    // B-frag (K): mats {n0-7 klo, n0-7 khi, n8-15 klo, n8-15 khi}
    const uint32_t bRow = (uint32_t)(l7 + ((lane >> 4) & 1) * 8) * 80 + ((lane >> 3) & 1) * 16;
    // B-frag (V, trans): lanes0-15 rows k, lanes16-31 dims+8
    const uint32_t vRow = (uint32_t)(lane & 15) * 80 + ((lane >> 4) & 1) * 16;

    const int q0 = w * 32;

#pragma unroll 1
    for (int mi = 0; mi < 2; mi++) {
        // ---- S = Q K^T (fp32 acc) ----
        float accs[8][4];
#pragma unroll
        for (int ni = 0; ni < 8; ni++)
#pragma unroll
            for (int c = 0; c < 4; c++) accs[ni][c] = 0.f;

        const uint32_t aBase = qsb + (uint32_t)(q0 + mi * 16) * 80 + aRow;
#pragma unroll
        for (int kt = 0; kt < 2; kt++) {
            uint32_t af[4];
            ldsm4(af, aBase + kt * 32);
#pragma unroll
            for (int nip = 0; nip < 4; nip++) {
                uint32_t bf[4];
                ldsm4(bf, ksb + (uint32_t)(nip * 16) * 80 + bRow + kt * 32);
                mma16(accs[2 * nip],     af, bf);
                mma16(accs[2 * nip + 1], af, bf + 2);
            }
        }

        // ---- scale + bias + mask + softmax (fp32) ----
        const int r0 = q0 + mi * 16 + g;
        const int r1 = r0 + 8;
        const int i0 = r0 >> 3, j0 = r0 & 7;
        const int i1 = r1 >> 3, j1 = r1 & 7;
        const int l0 = lab[r0], l1 = lab[r1];
        float mx0 = -1e30f, mx1 = -1e30f;
#pragma unroll
        for (int ni = 0; ni < 8; ni++) {
#pragma unroll
            for (int cc = 0; cc < 2; cc++) {
                const int col = 8 * ni + 2 * tig + cc;
                const int i2 = col >> 3, j2 = col & 7;
                const int lc = lab[col];
                float s0 = accs[ni][cc] * 0.17677669529663687f +
                           sbias[(i0 - i2 + 7) * 15 + (j0 - j2 + 7)];
                float s1 = accs[ni][2 + cc] * 0.17677669529663687f +
                           sbias[(i1 - i2 + 7) * 15 + (j1 - j2 + 7)];
                if (lc != l0) s0 -= 100.f;
                if (lc != l1) s1 -= 100.f;
                accs[ni][cc] = s0;
                accs[ni][2 + cc] = s1;
                mx0 = fmaxf(mx0, s0);
                mx1 = fmaxf(mx1, s1);
            }
        }
        mx0 = fmaxf(mx0, __shfl_xor_sync(0xffffffffu, mx0, 1));
        mx0 = fmaxf(mx0, __shfl_xor_sync(0xffffffffu, mx0, 2));
        mx1 = fmaxf(mx1, __shfl_xor_sync(0xffffffffu, mx1, 1));
        mx1 = fmaxf(mx1, __shfl_xor_sync(0xffffffffu, mx1, 2));
        float sum0 = 0.f, sum1 = 0.f;
#pragma unroll
        for (int ni = 0; ni < 8; ni++) {
#pragma unroll
            for (int cc = 0; cc < 2; cc++) {
                const float e0 = __expf(accs[ni][cc] - mx0);
                const float e1 = __expf(accs[ni][2 + cc] - mx1);
                accs[ni][cc] = e0;
                accs[ni][2 + cc] = e1;
                sum0 += e0;
                sum1 += e1;
            }
        }
        sum0 += __shfl_xor_sync(0xffffffffu, sum0, 1);
        sum0 += __shfl_xor_sync(0xffffffffu, sum0, 2);
        sum1 += __shfl_xor_sync(0xffffffffu, sum1, 1);
        sum1 += __shfl_xor_sync(0xffffffffu, sum1, 2);
        const float inv0 = __fdividef(1.f, sum0);
        const float inv1 = __fdividef(1.f, sum1);

        // ---- P fragments (C layout == A layout) ----
        uint32_t pa[4][4];
#pragma unroll
        for (int kt = 0; kt < 4; kt++) {
            __half2 h;
            h = __floats2half2_rn(accs[2 * kt][0] * inv0, accs[2 * kt][1] * inv0);
            pa[kt][0] = *(const uint32_t*)&h;
            h = __floats2half2_rn(accs[2 * kt][2] * inv1, accs[2 * kt][3] * inv1);
            pa[kt][1] = *(const uint32_t*)&h;
            h = __floats2half2_rn(accs[2 * kt + 1][0] * inv0, accs[2 * kt + 1][1] * inv0);
            pa[kt][2] = *(const uint32_t*)&h;
            h = __floats2half2_rn(accs[2 * kt + 1][2] * inv1, accs[2 * kt + 1][3] * inv1);
            pa[kt][3] = *(const uint32_t*)&h;
        }

        // ---- O = P V ----
        float acco[4][4];
#pragma unroll
        for (int nj = 0; nj < 4; nj++)
#pragma unroll
            for (int c = 0; c < 4; c++) acco[nj][c] = 0.f;
#pragma unroll
        for (int kt = 0; kt < 4; kt++) {
#pragma unroll
            for (int njp = 0; njp < 2; njp++) {
                uint32_t vb[4];
                ldsm4t(vb, vsb + (uint32_t)(kt * 16) * 80 + vRow + njp * 32);
                mma16(acco[2 * njp],     pa[kt], vb);
                mma16(acco[2 * njp + 1], pa[kt], vb + 2);
            }
        }

        // ---- write out ----
        __half* d0 = out + ((long)win * NPW + r0) * Cdim + head * HD;
        __half* d1 = out + ((long)win * NPW + r1) * Cdim + head * HD;
#pragma unroll
        for (int nj = 0; nj < 4; nj++) {
            const int col = 8 * nj + 2 * tig;
            *(__half2*)(d0 + col) = __floats2half2_rn(acco[nj][0], acco[nj][1]);
            *(__half2*)(d1 + col) = __floats2half2_rn(acco[nj][2], acco[nj][3]);
        }
    }
}

// ---------------------------------------------------------------------------
// Launch
// ---------------------------------------------------------------------------
extern "C" void kernel_launch(void* const* d_in, const int* in_sizes, int n_in,
                              void* d_out, int out_size)
{
    const float* x      = (const float*)d_in[0];
    const float* g1     = (const float*)d_in[1];
    const float* b1     = (const float*)d_in[2];
    const float* qkv_w  = (const float*)d_in[3];
    const float* qkv_b  = (const float*)d_in[4];
    const float* rpb    = (const float*)d_in[5];
    const float* proj_w = (const float*)d_in[6];
    const float* proj_b = (const float*)d_in[7];
    const float* g2     = (const float*)d_in[8];
    const float* b2     = (const float*)d_in[9];
    const float* fc1_w  = (const float*)d_in[10];
    const float* fc1_b  = (const float*)d_in[11];
    const float* fc2_w  = (const float*)d_in[12];
    const float* fc2_b  = (const float*)d_in[13];
    float* out = (float*)d_out;

    __half *p_qkv, *p_att, *p_ln2, *p_hh, *p_wh;
    float *p_x1;
    cudaGetSymbolAddress((void**)&p_qkv, g_qkv);
    cudaGetSymbolAddress((void**)&p_att, g_att);
    cudaGetSymbolAddress((void**)&p_ln2, g_ln2);
    cudaGetSymbolAddress((void**)&p_hh,  g_hh);
    cudaGetSymbolAddress((void**)&p_x1,  g_x1);
    cudaGetSymbolAddress((void**)&p_wh,  g_wh);

    static bool attr_set = false;
    if (!attr_set) {
        cudaFuncSetAttribute(gemm_ln,   cudaFuncAttributeMaxDynamicSharedMemorySize, LN_SMEM);
        cudaFuncSetAttribute(gemm_ha,   cudaFuncAttributeMaxDynamicSharedMemorySize, HA_SMEM);
        cudaFuncSetAttribute(gemm_h<3>, cudaFuncAttributeMaxDynamicSharedMemorySize, GEMM_SMEM);
        cudaFuncSetAttribute(gemm_h<2>, cudaFuncAttributeMaxDynamicSharedMemorySize, GEMM_SMEM);
        attr_set = true;
    }

    __half* w_qkv = p_wh;
    __half* w_prj = p_wh + 110592;
    __half* w_fc1 = p_wh + 147456;
    __half* w_fc2 = p_wh + 294912;

    // 0. weights fp32 -> fp16
    tohalf_all<<<442368 / 1024, 256>>>(qkv_w, proj_w, fc1_w, fc2_w, p_wh);

    const int M = NTOK;  // 131072, 2048 M-tiles of 64

    // 1. QKV (fused LN1 + shift/window gather)
    gemm_ln<<<M / 64, NTH, LN_SMEM>>>(x, w_qkv, qkv_b, g1, b1, p_qkv, 3 * Cdim);

    // 2. Window attention (mma.sync)
    attn_kernel<<<dim3(NWIN, NH), 64>>>(p_qkv, rpb, p_att);

    // 3. proj + unshift + x residual -> x1 fp32; fused LN2 -> ln2 fp16
    gemm_h<3><<<M / 64, NTH, GEMM_SMEM>>>(
        p_att, w_prj, proj_b, x, p_x1, p_ln2, g2, b2, Cdim, Cdim);

    // 4. FC1 + GELU (A-resident)
    gemm_ha<<<M / 64, NTH, HA_SMEM>>>(p_ln2, w_fc1, fc1_b, p_hh, HID);

    // 5. FC2 + x1 residual -> out fp32
    gemm_h<2><<<M / 64, NTH, GEMM_SMEM>>>(
        p_hh, w_fc2, fc2_b, p_x1, out, nullptr, nullptr, nullptr, Cdim, HID);
}